// round 1
// baseline (speedup 1.0000x reference)
#include <cuda_runtime.h>
#include <math.h>

// Problem constants
#define NB     4
#define CH     512
#define LSEQ   2048
#define NHEADS 8
#define DHEAD  64
#define QKV_CH 1536          // 3 * 512
#define ATT_SCALE 0.125f     // 64^-0.5

// ---------------------------------------------------------------------------
// Scratch (no cudaMalloc allowed): qkv = [N, 1536, L], att = [N, 512, L]
// ---------------------------------------------------------------------------
__device__ float g_qkv[(size_t)NB * QKV_CH * LSEQ];   // ~50 MB
__device__ float g_att[(size_t)NB * CH * LSEQ];       // ~17 MB

// ---------------------------------------------------------------------------
// Classic 128x128x8 SGEMM, 256 threads, 8x8 microtile (split 4x4 quadrants).
// C[z] = A @ B[z] (+ bias per-row).  A: MxK row-major (shared over z),
// B: KxN row-major, C: MxN row-major. M,N multiples of 128; K multiple of 8.
// ---------------------------------------------------------------------------
__global__ __launch_bounds__(256, 2)
void sgemm128x128(const float* __restrict__ A, const float* __restrict__ B,
                  float* __restrict__ C, const float* __restrict__ bias,
                  int M, int N, int K, long strideB, long strideC)
{
    __shared__ float As[8][128];
    __shared__ float Bs[8][128];

    const int t  = threadIdx.x;
    const int tx = t & 15;
    const int ty = t >> 4;
    const int bm = blockIdx.y * 128;
    const int bn = blockIdx.x * 128;

    B += (long)blockIdx.z * strideB;
    C += (long)blockIdx.z * strideC;

    const int arow = t >> 1;          // 0..127
    const int akk  = (t & 1) * 4;     // 0 or 4
    const int bkk  = t >> 5;          // 0..7
    const int bcol = (t & 31) * 4;    // 0..124

    float acc[8][8];
#pragma unroll
    for (int i = 0; i < 8; i++)
#pragma unroll
        for (int j = 0; j < 8; j++) acc[i][j] = 0.0f;

    for (int k0 = 0; k0 < K; k0 += 8) {
        float4 av = *(const float4*)(A + (long)(bm + arow) * K + k0 + akk);
        float4 bv = *(const float4*)(B + (long)(k0 + bkk) * N + bn + bcol);
        __syncthreads();
        As[akk + 0][arow] = av.x;
        As[akk + 1][arow] = av.y;
        As[akk + 2][arow] = av.z;
        As[akk + 3][arow] = av.w;
        *(float4*)&Bs[bkk][bcol] = bv;
        __syncthreads();

#pragma unroll
        for (int kk = 0; kk < 8; kk++) {
            float ar[8], br[8];
            *(float4*)&ar[0] = *(const float4*)&As[kk][ty * 4];
            *(float4*)&ar[4] = *(const float4*)&As[kk][64 + ty * 4];
            *(float4*)&br[0] = *(const float4*)&Bs[kk][tx * 4];
            *(float4*)&br[4] = *(const float4*)&Bs[kk][64 + tx * 4];
#pragma unroll
            for (int i = 0; i < 8; i++)
#pragma unroll
                for (int j = 0; j < 8; j++)
                    acc[i][j] += ar[i] * br[j];
        }
    }

#pragma unroll
    for (int qi = 0; qi < 2; qi++) {
#pragma unroll
        for (int ii = 0; ii < 4; ii++) {
            const int row = bm + qi * 64 + ty * 4 + ii;
            const float bval = bias ? bias[row] : 0.0f;
#pragma unroll
            for (int qj = 0; qj < 2; qj++) {
                const int col = bn + qj * 64 + tx * 4;
                float4 o;
                o.x = acc[qi * 4 + ii][qj * 4 + 0] + bval;
                o.y = acc[qi * 4 + ii][qj * 4 + 1] + bval;
                o.z = acc[qi * 4 + ii][qj * 4 + 2] + bval;
                o.w = acc[qi * 4 + ii][qj * 4 + 3] + bval;
                *(float4*)(C + (long)row * N + col) = o;
            }
        }
    }
}

// ---------------------------------------------------------------------------
// Flash attention, fp32. One block per (q-tile of 64, n*8+h).
// qkv layout: [n, 1536, L]; q = rows [0,512), k = [512,1024), v = [1024,1536),
// head h occupies rows h*64..h*64+63 within each third.
// Output layout: att[n, h*64+d, l]  (matches the reference's (h c) l transpose)
// smem: Qs[64][68] (d,i), Ks[64][68] (d,j), Vt[64][68] (j,d), Ps[64][68] (i,j)
// ---------------------------------------------------------------------------
#define FP 68
#define FLASH_SMEM (4 * 64 * FP * (int)sizeof(float))

__global__ __launch_bounds__(256)
void flash_kernel(const float* __restrict__ qkv, float* __restrict__ out)
{
    extern __shared__ float sm[];
    float (*Qs)[FP] = (float(*)[FP])(sm);
    float (*Ks)[FP] = (float(*)[FP])(sm + 64 * FP);
    float (*Vt)[FP] = (float(*)[FP])(sm + 2 * 64 * FP);
    float (*Ps)[FP] = (float(*)[FP])(sm + 3 * 64 * FP);

    const int t  = threadIdx.x;
    const int tx = t & 15;        // j / d quadrant: 4 cols
    const int ty = t >> 4;        // i quadrant: 4 rows
    const int i0 = blockIdx.x * 64;
    const int nh = blockIdx.y;
    const int n  = nh >> 3;
    const int h  = nh & 7;

    const float* qb = qkv + ((size_t)n * QKV_CH + h * DHEAD) * LSEQ;
    const float* kb = qb + (size_t)CH * LSEQ;
    const float* vb = qb + (size_t)(2 * CH) * LSEQ;

    // load Q tile (scaled): Qs[d][i]
    {
        const int d  = t >> 2;           // 0..63
        const int ic = (t & 3) * 16;     // 0,16,32,48
        const float* src = qb + (size_t)d * LSEQ + i0 + ic;
#pragma unroll
        for (int r = 0; r < 4; r++) {
            float4 v = *(const float4*)(src + r * 4);
            v.x *= ATT_SCALE; v.y *= ATT_SCALE; v.z *= ATT_SCALE; v.w *= ATT_SCALE;
            *(float4*)&Qs[d][ic + r * 4] = v;
        }
    }

    float m[4], lsum[4], acc[4][4];
#pragma unroll
    for (int ii = 0; ii < 4; ii++) {
        m[ii] = -INFINITY; lsum[ii] = 0.0f;
#pragma unroll
        for (int dd = 0; dd < 4; dd++) acc[ii][dd] = 0.0f;
    }

    for (int j0 = 0; j0 < LSEQ; j0 += 64) {
        __syncthreads();   // prev-iter Ks/Vt/Ps reads done; Q load done on iter 0

        // load K tile Ks[d][j] and V tile transposed Vt[j][d]
        {
            const int d  = t >> 2;
            const int jc = (t & 3) * 16;
            const float* ks = kb + (size_t)d * LSEQ + j0 + jc;
            const float* vs = vb + (size_t)d * LSEQ + j0 + jc;
#pragma unroll
            for (int r = 0; r < 4; r++) {
                *(float4*)&Ks[d][jc + r * 4] = *(const float4*)(ks + r * 4);
                float4 vv = *(const float4*)(vs + r * 4);
                Vt[jc + r * 4 + 0][d] = vv.x;
                Vt[jc + r * 4 + 1][d] = vv.y;
                Vt[jc + r * 4 + 2][d] = vv.z;
                Vt[jc + r * 4 + 3][d] = vv.w;
            }
        }
        __syncthreads();

        // S = Q^T K : s[ii][jj] for i = ty*4+ii, j = tx*4+jj
        float s[4][4];
#pragma unroll
        for (int ii = 0; ii < 4; ii++)
#pragma unroll
            for (int jj = 0; jj < 4; jj++) s[ii][jj] = 0.0f;

#pragma unroll 16
        for (int dd = 0; dd < 64; dd++) {
            float qa[4], kk4[4];
            *(float4*)&qa[0]  = *(const float4*)&Qs[dd][ty * 4];
            *(float4*)&kk4[0] = *(const float4*)&Ks[dd][tx * 4];
#pragma unroll
            for (int ii = 0; ii < 4; ii++)
#pragma unroll
                for (int jj = 0; jj < 4; jj++)
                    s[ii][jj] += qa[ii] * kk4[jj];
        }

        // online softmax: row reductions across 16 lanes (tx dimension)
        float rm[4], rs[4], alpha[4];
#pragma unroll
        for (int ii = 0; ii < 4; ii++) {
            float v = fmaxf(fmaxf(s[ii][0], s[ii][1]), fmaxf(s[ii][2], s[ii][3]));
#pragma unroll
            for (int off = 8; off >= 1; off >>= 1)
                v = fmaxf(v, __shfl_xor_sync(0xffffffffu, v, off));
            rm[ii] = v;
        }
#pragma unroll
        for (int ii = 0; ii < 4; ii++) {
            const float mnew = fmaxf(m[ii], rm[ii]);
            alpha[ii] = __expf(m[ii] - mnew);
            m[ii] = mnew;
            float rsum = 0.0f;
#pragma unroll
            for (int jj = 0; jj < 4; jj++) {
                const float p = __expf(s[ii][jj] - mnew);
                s[ii][jj] = p;
                rsum += p;
            }
            rs[ii] = rsum;
        }
#pragma unroll
        for (int ii = 0; ii < 4; ii++) {
            float v = rs[ii];
#pragma unroll
            for (int off = 8; off >= 1; off >>= 1)
                v += __shfl_xor_sync(0xffffffffu, v, off);
            lsum[ii] = lsum[ii] * alpha[ii] + v;
#pragma unroll
            for (int dd = 0; dd < 4; dd++) acc[ii][dd] *= alpha[ii];
        }

        // stage P to smem
#pragma unroll
        for (int ii = 0; ii < 4; ii++) {
            float4 pv = make_float4(s[ii][0], s[ii][1], s[ii][2], s[ii][3]);
            *(float4*)&Ps[ty * 4 + ii][tx * 4] = pv;
        }
        __syncthreads();

        // O += P @ V^T : acc[ii][dd] += sum_j Ps[i][j] * Vt[j][d]
#pragma unroll 8
        for (int j = 0; j < 64; j++) {
            float vv[4];
            *(float4*)&vv[0] = *(const float4*)&Vt[j][tx * 4];
            float pa[4];
#pragma unroll
            for (int ii = 0; ii < 4; ii++) pa[ii] = Ps[ty * 4 + ii][j];
#pragma unroll
            for (int ii = 0; ii < 4; ii++)
#pragma unroll
                for (int dd = 0; dd < 4; dd++)
                    acc[ii][dd] += pa[ii] * vv[dd];
        }
    }

    // epilogue: out[n, h*64 + d, i] = acc / l
    float inv[4];
#pragma unroll
    for (int ii = 0; ii < 4; ii++) inv[ii] = 1.0f / lsum[ii];

#pragma unroll
    for (int dd = 0; dd < 4; dd++) {
        const int chn = n * CH + h * DHEAD + tx * 4 + dd;
        float4 w;
        w.x = acc[0][dd] * inv[0];
        w.y = acc[1][dd] * inv[1];
        w.z = acc[2][dd] * inv[2];
        w.w = acc[3][dd] * inv[3];
        *(float4*)(out + (size_t)chn * LSEQ + i0 + ty * 4) = w;
    }
}

// ---------------------------------------------------------------------------
// Launch
// ---------------------------------------------------------------------------
extern "C" void kernel_launch(void* const* d_in, const int* in_sizes, int n_in,
                              void* d_out, int out_size)
{
    const float* x     = (const float*)d_in[0];   // [4, 512, 2048]
    const float* w_qkv = (const float*)d_in[1];   // [1536, 512]
    const float* w_out = (const float*)d_in[2];   // [512, 512]
    const float* b_out = (const float*)d_in[3];   // [512]
    float* out = (float*)d_out;                   // [4, 512, 2048]

    float *qkv = nullptr, *att = nullptr;
    cudaGetSymbolAddress((void**)&qkv, g_qkv);
    cudaGetSymbolAddress((void**)&att, g_att);

    cudaFuncSetAttribute(flash_kernel,
                         cudaFuncAttributeMaxDynamicSharedMemorySize, FLASH_SMEM);

    // 1) qkv[n] = w_qkv @ x[n]
    {
        dim3 grid(LSEQ / 128, QKV_CH / 128, NB);
        sgemm128x128<<<grid, 256>>>(w_qkv, x, qkv, nullptr,
                                    QKV_CH, LSEQ, CH,
                                    (long)CH * LSEQ, (long)QKV_CH * LSEQ);
    }
    // 2) flash attention -> att[n, (h d), l]
    {
        dim3 grid(LSEQ / 64, NB * NHEADS);
        flash_kernel<<<grid, 256, FLASH_SMEM>>>(qkv, att);
    }
    // 3) out[n] = w_out @ att[n] + b_out
    {
        dim3 grid(LSEQ / 128, CH / 128, NB);
        sgemm128x128<<<grid, 256>>>(w_out, att, out, b_out,
                                    CH, LSEQ, CH,
                                    (long)CH * LSEQ, (long)CH * LSEQ);
    }
}

// round 2
// speedup vs baseline: 1.8764x; 1.8764x over previous
#include <cuda_runtime.h>
#include <math.h>
#include <stdint.h>

#define NB     4
#define CH     512
#define LSEQ   2048
#define NHEADS 8
#define DHEAD  64
#define QKV_CH 1536
#define ATT_SCALE 0.125f

// Scratch (no cudaMalloc allowed)
__device__ float g_qkv[(size_t)NB * QKV_CH * LSEQ];   // ~50 MB
__device__ float g_att[(size_t)NB * CH * LSEQ];       // ~17 MB

// ---------------------------------------------------------------------------
// tf32 helpers
// ---------------------------------------------------------------------------
__device__ __forceinline__ float tf32r(float x) {
    uint32_t u;
    asm("cvt.rna.tf32.f32 %0, %1;" : "=r"(u) : "f"(x));
    return __uint_as_float(u);
}

__device__ __forceinline__ void mma_tf32(float c[4],
    uint32_t a0, uint32_t a1, uint32_t a2, uint32_t a3,
    uint32_t b0, uint32_t b1)
{
    asm volatile(
        "mma.sync.aligned.m16n8k8.row.col.f32.tf32.tf32.f32 "
        "{%0,%1,%2,%3}, {%4,%5,%6,%7}, {%8,%9}, {%0,%1,%2,%3};"
        : "+f"(c[0]), "+f"(c[1]), "+f"(c[2]), "+f"(c[3])
        : "r"(a0), "r"(a1), "r"(a2), "r"(a3), "r"(b0), "r"(b1));
}

// ---------------------------------------------------------------------------
// GEMM: C[z] = A @ B[z] (+bias). A: MxK row-major (shared), B: KxN row-major.
// Block 128x128, K-step 16, 8 warps (2m x 4n), warp tile 64x32, tf32 mma.
// smem [k][m] stride 136 (== 8 mod 32) -> conflict-free scalar fragment LDS.
// ---------------------------------------------------------------------------
__global__ __launch_bounds__(256)
void gemm_tc(const float* __restrict__ A, const float* __restrict__ B,
             float* __restrict__ C, const float* __restrict__ bias,
             int M, int N, int K, long strideB, long strideC)
{
    __shared__ float As[16][136];
    __shared__ float Bs[16][136];

    const int t    = threadIdx.x;
    const int lane = t & 31;
    const int w    = t >> 5;
    const int qr   = lane >> 2;   // 0..7
    const int qc   = lane & 3;    // 0..3
    const int bm   = blockIdx.y * 128;
    const int bn   = blockIdx.x * 128;

    B += (long)blockIdx.z * strideB;
    C += (long)blockIdx.z * strideC;

    const int wm = (w >> 2) * 64;
    const int wn = (w & 3) * 32;

    const int ar  = t >> 1;         // A stage: row 0..127
    const int akc = (t & 1) * 8;    // k sub 0 or 8
    const int bkr = t >> 4;         // B stage: k row 0..15
    const int bnc = (t & 15) * 8;   // n sub

    float acc[4][4][4];
#pragma unroll
    for (int i = 0; i < 4; i++)
#pragma unroll
        for (int j = 0; j < 4; j++)
#pragma unroll
            for (int r = 0; r < 4; r++) acc[i][j][r] = 0.0f;

    // prefetch first K-slab into registers
    float4 a0r = *(const float4*)(A + (size_t)(bm + ar) * K + akc);
    float4 a1r = *(const float4*)(A + (size_t)(bm + ar) * K + akc + 4);
    float4 b0r = *(const float4*)(B + (size_t)bkr * N + bn + bnc);
    float4 b1r = *(const float4*)(B + (size_t)bkr * N + bn + bnc + 4);

    for (int k0 = 0; k0 < K; k0 += 16) {
        __syncthreads();
        As[akc + 0][ar] = tf32r(a0r.x);
        As[akc + 1][ar] = tf32r(a0r.y);
        As[akc + 2][ar] = tf32r(a0r.z);
        As[akc + 3][ar] = tf32r(a0r.w);
        As[akc + 4][ar] = tf32r(a1r.x);
        As[akc + 5][ar] = tf32r(a1r.y);
        As[akc + 6][ar] = tf32r(a1r.z);
        As[akc + 7][ar] = tf32r(a1r.w);
        {
            float4 c0 = make_float4(tf32r(b0r.x), tf32r(b0r.y), tf32r(b0r.z), tf32r(b0r.w));
            float4 c1 = make_float4(tf32r(b1r.x), tf32r(b1r.y), tf32r(b1r.z), tf32r(b1r.w));
            *(float4*)&Bs[bkr][bnc]     = c0;
            *(float4*)&Bs[bkr][bnc + 4] = c1;
        }
        __syncthreads();

        if (k0 + 16 < K) {
            const int kn = k0 + 16;
            a0r = *(const float4*)(A + (size_t)(bm + ar) * K + kn + akc);
            a1r = *(const float4*)(A + (size_t)(bm + ar) * K + kn + akc + 4);
            b0r = *(const float4*)(B + (size_t)(kn + bkr) * N + bn + bnc);
            b1r = *(const float4*)(B + (size_t)(kn + bkr) * N + bn + bnc + 4);
        }

#pragma unroll
        for (int ks = 0; ks < 16; ks += 8) {
            uint32_t af[4][4];
#pragma unroll
            for (int mf = 0; mf < 4; mf++) {
                const int mi = wm + mf * 16 + qr;
                af[mf][0] = __float_as_uint(As[ks + qc][mi]);
                af[mf][1] = __float_as_uint(As[ks + qc][mi + 8]);
                af[mf][2] = __float_as_uint(As[ks + qc + 4][mi]);
                af[mf][3] = __float_as_uint(As[ks + qc + 4][mi + 8]);
            }
#pragma unroll
            for (int nf = 0; nf < 4; nf++) {
                const int ni = wn + nf * 8 + qr;
                uint32_t b0 = __float_as_uint(Bs[ks + qc][ni]);
                uint32_t b1 = __float_as_uint(Bs[ks + qc + 4][ni]);
#pragma unroll
                for (int mf = 0; mf < 4; mf++)
                    mma_tf32(acc[mf][nf], af[mf][0], af[mf][1], af[mf][2], af[mf][3], b0, b1);
            }
        }
    }

#pragma unroll
    for (int mf = 0; mf < 4; mf++) {
        const int row = bm + wm + mf * 16 + qr;
        const float bv0 = bias ? bias[row]     : 0.0f;
        const float bv1 = bias ? bias[row + 8] : 0.0f;
#pragma unroll
        for (int nf = 0; nf < 4; nf++) {
            const int col = bn + wn + nf * 8 + qc * 2;
            float2 o0 = make_float2(acc[mf][nf][0] + bv0, acc[mf][nf][1] + bv0);
            float2 o1 = make_float2(acc[mf][nf][2] + bv1, acc[mf][nf][3] + bv1);
            *(float2*)(C + (size_t)row * N + col)       = o0;
            *(float2*)(C + (size_t)(row + 8) * N + col) = o1;
        }
    }
}

// ---------------------------------------------------------------------------
// Flash attention, tf32 mma. Bq = Bk = 64, 128 threads (4 warps x m16n64).
// Layouts: Qs/Ks [d][i|j] stride 72 (==8 mod 32), Vt [j][d] stride 72,
// Ps [i][j] stride 68 (==4 mod 32). All fragment LDS bank-conflict-free.
// Output written as att[n, h*64+d, l].
// ---------------------------------------------------------------------------
#define FQI 72
#define FPJ 68
#define FL_SMEM ((3 * 64 * FQI + 64 * FPJ) * (int)sizeof(float))   // 72704 B

__global__ __launch_bounds__(128)
void flash_tc(const float* __restrict__ qkv, float* __restrict__ out)
{
    extern __shared__ float sm[];
    float (*Qs)[FQI] = (float(*)[FQI])sm;
    float (*Ks)[FQI] = (float(*)[FQI])(sm + 64 * FQI);
    float (*Vt)[FQI] = (float(*)[FQI])(sm + 2 * 64 * FQI);
    float (*Ps)[FPJ] = (float(*)[FPJ])(sm + 3 * 64 * FQI);

    const int t    = threadIdx.x;
    const int lane = t & 31;
    const int w    = t >> 5;      // 0..3
    const int qr   = lane >> 2;   // 0..7
    const int qc   = lane & 3;    // 0..3
    const int i0   = blockIdx.x * 64;
    const int nh   = blockIdx.y;
    const int n    = nh >> 3, h = nh & 7;

    const float* qb = qkv + ((size_t)n * QKV_CH + h * DHEAD) * LSEQ;
    const float* kb = qb + (size_t)CH * LSEQ;
    const float* vb = qb + 2 * (size_t)CH * LSEQ;

    // stage Q [d][i], scaled + tf32
    {
        const int d  = t >> 1;
        const int ic = (t & 1) * 32;
        const float* src = qb + (size_t)d * LSEQ + i0 + ic;
#pragma unroll
        for (int m = 0; m < 8; m++) {
            float4 v = *(const float4*)(src + m * 4);
            float4 o = make_float4(tf32r(v.x * ATT_SCALE), tf32r(v.y * ATT_SCALE),
                                   tf32r(v.z * ATT_SCALE), tf32r(v.w * ATT_SCALE));
            *(float4*)&Qs[d][ic + m * 4] = o;
        }
    }

    const int mrow = w * 16;
    float m0 = -1e30f, m1 = -1e30f, l0 = 0.0f, l1 = 0.0f;
    float o[8][4];
#pragma unroll
    for (int df = 0; df < 8; df++)
#pragma unroll
        for (int r = 0; r < 4; r++) o[df][r] = 0.0f;

    for (int j0 = 0; j0 < LSEQ; j0 += 64) {
        __syncthreads();
        // stage K [d][j]
        {
            const int d  = t >> 1;
            const int jc = (t & 1) * 32;
            const float* src = kb + (size_t)d * LSEQ + j0 + jc;
#pragma unroll
            for (int m = 0; m < 8; m++) {
                float4 v = *(const float4*)(src + m * 4);
                float4 c = make_float4(tf32r(v.x), tf32r(v.y), tf32r(v.z), tf32r(v.w));
                *(float4*)&Ks[d][jc + m * 4] = c;
            }
        }
        // stage V transposed [j][d] (lanes span consecutive d -> conflict-free)
        {
            const int d  = t & 63;
            const int jb = (t >> 6) * 32;
            const float* src = vb + (size_t)d * LSEQ + j0 + jb;
#pragma unroll
            for (int m = 0; m < 8; m++) {
                float4 v = *(const float4*)(src + m * 4);
                Vt[jb + m * 4 + 0][d] = tf32r(v.x);
                Vt[jb + m * 4 + 1][d] = tf32r(v.y);
                Vt[jb + m * 4 + 2][d] = tf32r(v.z);
                Vt[jb + m * 4 + 3][d] = tf32r(v.w);
            }
        }
        __syncthreads();

        // S = Q^T K  (warp: rows [mrow, mrow+16), cols 0..63)
        float s[8][4];
#pragma unroll
        for (int nf = 0; nf < 8; nf++)
#pragma unroll
            for (int r = 0; r < 4; r++) s[nf][r] = 0.0f;

#pragma unroll
        for (int kk = 0; kk < 64; kk += 8) {
            uint32_t a0 = __float_as_uint(Qs[kk + qc][mrow + qr]);
            uint32_t a1 = __float_as_uint(Qs[kk + qc][mrow + qr + 8]);
            uint32_t a2 = __float_as_uint(Qs[kk + qc + 4][mrow + qr]);
            uint32_t a3 = __float_as_uint(Qs[kk + qc + 4][mrow + qr + 8]);
#pragma unroll
            for (int nf = 0; nf < 8; nf++) {
                uint32_t b0 = __float_as_uint(Ks[kk + qc][nf * 8 + qr]);
                uint32_t b1 = __float_as_uint(Ks[kk + qc + 4][nf * 8 + qr]);
                mma_tf32(s[nf], a0, a1, a2, a3, b0, b1);
            }
        }

        // online softmax (rows mrow+qr and mrow+qr+8)
        float rm0 = -1e30f, rm1 = -1e30f;
#pragma unroll
        for (int nf = 0; nf < 8; nf++) {
            rm0 = fmaxf(rm0, fmaxf(s[nf][0], s[nf][1]));
            rm1 = fmaxf(rm1, fmaxf(s[nf][2], s[nf][3]));
        }
        rm0 = fmaxf(rm0, __shfl_xor_sync(0xffffffffu, rm0, 1));
        rm0 = fmaxf(rm0, __shfl_xor_sync(0xffffffffu, rm0, 2));
        rm1 = fmaxf(rm1, __shfl_xor_sync(0xffffffffu, rm1, 1));
        rm1 = fmaxf(rm1, __shfl_xor_sync(0xffffffffu, rm1, 2));

        const float mn0 = fmaxf(m0, rm0), mn1 = fmaxf(m1, rm1);
        const float al0 = __expf(m0 - mn0), al1 = __expf(m1 - mn1);
        m0 = mn0; m1 = mn1;

        float rs0 = 0.0f, rs1 = 0.0f;
#pragma unroll
        for (int nf = 0; nf < 8; nf++) {
            s[nf][0] = __expf(s[nf][0] - mn0);
            s[nf][1] = __expf(s[nf][1] - mn0);
            s[nf][2] = __expf(s[nf][2] - mn1);
            s[nf][3] = __expf(s[nf][3] - mn1);
            rs0 += s[nf][0] + s[nf][1];
            rs1 += s[nf][2] + s[nf][3];
        }
        rs0 += __shfl_xor_sync(0xffffffffu, rs0, 1);
        rs0 += __shfl_xor_sync(0xffffffffu, rs0, 2);
        rs1 += __shfl_xor_sync(0xffffffffu, rs1, 1);
        rs1 += __shfl_xor_sync(0xffffffffu, rs1, 2);

        l0 = l0 * al0 + rs0;
        l1 = l1 * al1 + rs1;
#pragma unroll
        for (int df = 0; df < 8; df++) {
            o[df][0] *= al0; o[df][1] *= al0;
            o[df][2] *= al1; o[df][3] *= al1;
        }

        // stage P (tf32) into warp-private rows of Ps
#pragma unroll
        for (int nf = 0; nf < 8; nf++) {
            *(float2*)&Ps[mrow + qr][nf * 8 + qc * 2] =
                make_float2(tf32r(s[nf][0]), tf32r(s[nf][1]));
            *(float2*)&Ps[mrow + qr + 8][nf * 8 + qc * 2] =
                make_float2(tf32r(s[nf][2]), tf32r(s[nf][3]));
        }
        __syncwarp();

        // O += P @ V^T
#pragma unroll
        for (int kk = 0; kk < 64; kk += 8) {
            uint32_t a0 = __float_as_uint(Ps[mrow + qr][kk + qc]);
            uint32_t a1 = __float_as_uint(Ps[mrow + qr + 8][kk + qc]);
            uint32_t a2 = __float_as_uint(Ps[mrow + qr][kk + qc + 4]);
            uint32_t a3 = __float_as_uint(Ps[mrow + qr + 8][kk + qc + 4]);
#pragma unroll
            for (int df = 0; df < 8; df++) {
                uint32_t b0 = __float_as_uint(Vt[kk + qc][df * 8 + qr]);
                uint32_t b1 = __float_as_uint(Vt[kk + qc + 4][df * 8 + qr]);
                mma_tf32(o[df], a0, a1, a2, a3, b0, b1);
            }
        }
        __syncwarp();
    }

    // epilogue: out[n, h*64 + d, i] = O / l
    const float inv0 = 1.0f / l0, inv1 = 1.0f / l1;
    const int gi = i0 + mrow + qr;
#pragma unroll
    for (int df = 0; df < 8; df++) {
        const int col = n * CH + h * DHEAD + df * 8 + qc * 2;
        out[(size_t)col * LSEQ + gi]           = o[df][0] * inv0;
        out[(size_t)(col + 1) * LSEQ + gi]     = o[df][1] * inv0;
        out[(size_t)col * LSEQ + gi + 8]       = o[df][2] * inv1;
        out[(size_t)(col + 1) * LSEQ + gi + 8] = o[df][3] * inv1;
    }
}

// ---------------------------------------------------------------------------
// Launch
// ---------------------------------------------------------------------------
extern "C" void kernel_launch(void* const* d_in, const int* in_sizes, int n_in,
                              void* d_out, int out_size)
{
    const float* x     = (const float*)d_in[0];   // [4, 512, 2048]
    const float* w_qkv = (const float*)d_in[1];   // [1536, 512]
    const float* w_out = (const float*)d_in[2];   // [512, 512]
    const float* b_out = (const float*)d_in[3];   // [512]
    float* out = (float*)d_out;                   // [4, 512, 2048]

    float *qkv = nullptr, *att = nullptr;
    cudaGetSymbolAddress((void**)&qkv, g_qkv);
    cudaGetSymbolAddress((void**)&att, g_att);

    cudaFuncSetAttribute(flash_tc,
                         cudaFuncAttributeMaxDynamicSharedMemorySize, FL_SMEM);

    // 1) qkv[n] = w_qkv @ x[n]
    {
        dim3 grid(LSEQ / 128, QKV_CH / 128, NB);
        gemm_tc<<<grid, 256>>>(w_qkv, x, qkv, nullptr,
                               QKV_CH, LSEQ, CH,
                               (long)CH * LSEQ, (long)QKV_CH * LSEQ);
    }
    // 2) flash attention -> att[n, (h d), l]
    {
        dim3 grid(LSEQ / 64, NB * NHEADS);
        flash_tc<<<grid, 128, FL_SMEM>>>(qkv, att);
    }
    // 3) out[n] = w_out @ att[n] + b_out
    {
        dim3 grid(LSEQ / 128, CH / 128, NB);
        gemm_tc<<<grid, 256>>>(w_out, att, out, b_out,
                               CH, LSEQ, CH,
                               (long)CH * LSEQ, (long)CH * LSEQ);
    }
}

// round 3
// speedup vs baseline: 3.4191x; 1.8222x over previous
#include <cuda_runtime.h>
#include <math.h>
#include <stdint.h>

#define NB     4
#define CH     512
#define LSEQ   2048
#define NHEADS 8
#define DHEAD  64
#define QKV_CH 1536

// ---------------------------------------------------------------------------
// Scratch (no cudaMalloc allowed)
// ---------------------------------------------------------------------------
__device__ float g_qkv[(size_t)NB * QKV_CH * LSEQ];   // ~50 MB  (tf32-rounded)
__device__ float g_att[(size_t)NB * CH * LSEQ];       // ~17 MB  (tf32-rounded)
__device__ float g_x[(size_t)NB * CH * LSEQ];         // ~17 MB  (tf32-rounded x)
__device__ float g_wqkvT[CH * QKV_CH];                // w_qkv^T, rounded
__device__ float g_woutT[CH * CH];                    // w_out^T, rounded

// ---------------------------------------------------------------------------
// helpers
// ---------------------------------------------------------------------------
__device__ __forceinline__ float tf32r(float x) {
    uint32_t u;
    asm("cvt.rna.tf32.f32 %0, %1;" : "=r"(u) : "f"(x));
    return __uint_as_float(u);
}
__device__ __forceinline__ uint32_t fau(float x) { return __float_as_uint(x); }

__device__ __forceinline__ void mma_tf32(float c[4],
    uint32_t a0, uint32_t a1, uint32_t a2, uint32_t a3,
    uint32_t b0, uint32_t b1)
{
    asm volatile(
        "mma.sync.aligned.m16n8k8.row.col.f32.tf32.tf32.f32 "
        "{%0,%1,%2,%3}, {%4,%5,%6,%7}, {%8,%9}, {%0,%1,%2,%3};"
        : "+f"(c[0]), "+f"(c[1]), "+f"(c[2]), "+f"(c[3])
        : "r"(a0), "r"(a1), "r"(a2), "r"(a3), "r"(b0), "r"(b1));
}

__device__ __forceinline__ void cp128(uint32_t dst, const void* src) {
    asm volatile("cp.async.cg.shared.global [%0], [%1], 16;" :: "r"(dst), "l"(src));
}
#define CP_COMMIT() asm volatile("cp.async.commit_group;")
#define CP_WAIT(N)  asm volatile("cp.async.wait_group %0;" :: "n"(N))

// ---------------------------------------------------------------------------
// prep kernels: tf32-round x; transpose+round weights
// ---------------------------------------------------------------------------
__global__ void round4_kernel(const float4* __restrict__ in, float4* __restrict__ out, int n4)
{
    int i = blockIdx.x * blockDim.x + threadIdx.x;
    if (i < n4) {
        float4 v = in[i];
        out[i] = make_float4(tf32r(v.x), tf32r(v.y), tf32r(v.z), tf32r(v.w));
    }
}

// in: [M][K] row-major -> out: [K][M] row-major, tf32-rounded
__global__ void transpose_round(const float* __restrict__ in, float* __restrict__ out,
                                int M, int K)
{
    __shared__ float tile[32][33];
    const int k0 = blockIdx.x * 32;
    const int m0 = blockIdx.y * 32;
    const int tx = threadIdx.x, ty = threadIdx.y;
#pragma unroll
    for (int r = 0; r < 32; r += 8)
        tile[ty + r][tx] = tf32r(in[(size_t)(m0 + ty + r) * K + k0 + tx]);
    __syncthreads();
#pragma unroll
    for (int r = 0; r < 32; r += 8)
        out[(size_t)(k0 + ty + r) * M + m0 + tx] = tile[tx][ty + r];
}

// ---------------------------------------------------------------------------
// GEMM: C[z] = A @ B[z] (+bias). AT: KxM row-major (A transposed, pre-rounded),
// B: KxN row-major (pre-rounded). 128x128 tile, k-step 16, 3-stage cp.async.
// 8 warps (2m x 4n), warp tile 64x32, m16n8k8 tf32.
// ---------------------------------------------------------------------------
#define GP     136
#define GSTG   (16 * GP)                    // words per stage per matrix
#define G_SMEM (2 * 3 * GSTG * (int)sizeof(float))   // 52224 B

__global__ __launch_bounds__(256, 2)
void gemm_cp(const float* __restrict__ AT, const float* __restrict__ B,
             float* __restrict__ C, const float* __restrict__ bias,
             int M, int N, int K, long strideB, long strideC, int round_out)
{
    extern __shared__ float gsm[];
    float* Asm = gsm;                 // [3][16][136]
    float* Bsm = gsm + 3 * GSTG;      // [3][16][136]

    const int t    = threadIdx.x;
    const int lane = t & 31;
    const int w    = t >> 5;
    const int qr   = lane >> 2;
    const int qc   = lane & 3;
    const int bm   = blockIdx.y * 128;
    const int bn   = blockIdx.x * 128;

    B += (long)blockIdx.z * strideB;
    C += (long)blockIdx.z * strideC;

    const int wm = (w >> 2) * 64;
    const int wn = (w & 3) * 32;

    const uint32_t aBase = (uint32_t)__cvta_generic_to_shared(Asm);
    const uint32_t bBase = (uint32_t)__cvta_generic_to_shared(Bsm);

    const int srow = t >> 4;          // 0..15
    const int scol = (t & 15) * 4;    // 0..60

    const int nslabs = K / 16;

    // stage slab `slab` into buffer `buf`
    auto stage = [&](int slab, int buf) {
        const float* aSrc = AT + (size_t)(slab * 16 + srow) * M + bm + scol;
        const float* bSrc = B  + (size_t)(slab * 16 + srow) * N + bn + scol;
        uint32_t aDst = aBase + (uint32_t)((buf * GSTG + srow * GP + scol) * 4);
        uint32_t bDst = bBase + (uint32_t)((buf * GSTG + srow * GP + scol) * 4);
        cp128(aDst,       aSrc);
        cp128(aDst + 256, aSrc + 64);
        cp128(bDst,       bSrc);
        cp128(bDst + 256, bSrc + 64);
    };

    float acc[4][4][4];
#pragma unroll
    for (int i = 0; i < 4; i++)
#pragma unroll
        for (int j = 0; j < 4; j++)
#pragma unroll
            for (int r = 0; r < 4; r++) acc[i][j][r] = 0.0f;

    stage(0, 0); CP_COMMIT();
    stage(1, 1); CP_COMMIT();

    for (int i = 0; i < nslabs; i++) {
        const int s = i % 3;
        if (i + 2 < nslabs) { stage(i + 2, (i + 2) % 3); CP_COMMIT(); CP_WAIT(2); }
        else if (i + 1 < nslabs) { CP_WAIT(1); }
        else { CP_WAIT(0); }
        __syncthreads();

        const float* As = Asm + s * GSTG;
        const float* Bs = Bsm + s * GSTG;

#pragma unroll
        for (int ks = 0; ks < 16; ks += 8) {
            uint32_t af[4][4];
#pragma unroll
            for (int mf = 0; mf < 4; mf++) {
                const int mi = wm + mf * 16 + qr;
                af[mf][0] = fau(As[(ks + qc)     * GP + mi]);
                af[mf][1] = fau(As[(ks + qc)     * GP + mi + 8]);
                af[mf][2] = fau(As[(ks + qc + 4) * GP + mi]);
                af[mf][3] = fau(As[(ks + qc + 4) * GP + mi + 8]);
            }
#pragma unroll
            for (int nf = 0; nf < 4; nf++) {
                const int ni = wn + nf * 8 + qr;
                uint32_t b0 = fau(Bs[(ks + qc)     * GP + ni]);
                uint32_t b1 = fau(Bs[(ks + qc + 4) * GP + ni]);
#pragma unroll
                for (int mf = 0; mf < 4; mf++)
                    mma_tf32(acc[mf][nf], af[mf][0], af[mf][1], af[mf][2], af[mf][3], b0, b1);
            }
        }
        __syncthreads();   // all reads of buf s done before it is refilled
    }

#pragma unroll
    for (int mf = 0; mf < 4; mf++) {
        const int row = bm + wm + mf * 16 + qr;
        const float bv0 = bias ? bias[row]     : 0.0f;
        const float bv1 = bias ? bias[row + 8] : 0.0f;
#pragma unroll
        for (int nf = 0; nf < 4; nf++) {
            const int col = bn + wn + nf * 8 + qc * 2;
            float o00 = acc[mf][nf][0] + bv0, o01 = acc[mf][nf][1] + bv0;
            float o10 = acc[mf][nf][2] + bv1, o11 = acc[mf][nf][3] + bv1;
            if (round_out) {
                o00 = tf32r(o00); o01 = tf32r(o01);
                o10 = tf32r(o10); o11 = tf32r(o11);
            }
            *(float2*)(C + (size_t)row * N + col)       = make_float2(o00, o01);
            *(float2*)(C + (size_t)(row + 8) * N + col) = make_float2(o10, o11);
        }
    }
}

// ---------------------------------------------------------------------------
// Flash attention v3: Bq=128, 256 threads (8 warps x m16n64), Bk=64.
// Q staged once in fragment-major smem (LDS.128 per A-frag).
// K/V double-buffered via cp.async (K pad 72, V pad 68 -> conflict-free frags).
// P never touches smem: shfl-permuted from S registers into PV A-fragments.
// All inputs pre-rounded tf32; output written tf32-rounded.
// ---------------------------------------------------------------------------
#define KP        72
#define VP        68
#define QF_WORDS  (8 * 8 * 32 * 4)          // 8192
#define KS_WORDS  (64 * KP)                 // 4608
#define VS_WORDS  (64 * VP)                 // 4352
#define FL_SMEM   ((QF_WORDS + 2 * KS_WORDS + 2 * VS_WORDS) * (int)sizeof(float)) // 104448

__global__ __launch_bounds__(256, 2)
void flash3(const float* __restrict__ qkv, float* __restrict__ out)
{
    extern __shared__ float sm[];
    float* Qf  = sm;                          // [kk=8][w=8][lane=32][4]
    float* KsA = sm + QF_WORDS;               // [2][64][72]
    float* VsA = KsA + 2 * KS_WORDS;          // [2][64][68]

    const int t    = threadIdx.x;
    const int lane = t & 31;
    const int w    = t >> 5;      // 0..7
    const int qr   = lane >> 2;   // 0..7
    const int qc   = lane & 3;    // 0..3
    const int i0   = blockIdx.x * 128;
    const int nh   = blockIdx.y;
    const int n    = nh >> 3, h = nh & 7;

    const float* qb = qkv + ((size_t)n * QKV_CH + h * DHEAD) * LSEQ;
    const float* kb = qb + (size_t)CH * LSEQ;
    const float* vb = qb + 2 * (size_t)CH * LSEQ;

    const uint32_t ksBase = (uint32_t)__cvta_generic_to_shared(KsA);
    const uint32_t vsBase = (uint32_t)__cvta_generic_to_shared(VsA);

    const int sd = t >> 2;        // staging row d: 0..63
    const int sc = t & 3;         // staging chunk

    auto stageKV = [&](int jt, int buf) {
        const float* ksrc = kb + (size_t)sd * LSEQ + jt * 64;
        const float* vsrc = vb + (size_t)sd * LSEQ + jt * 64;
        uint32_t kdst = ksBase + (uint32_t)((buf * KS_WORDS + sd * KP) * 4);
        uint32_t vdst = vsBase + (uint32_t)((buf * VS_WORDS + sd * VP) * 4);
#pragma unroll
        for (int c = 0; c < 4; c++) {
            const int j4 = (sc + 4 * c) * 4;
            cp128(kdst + j4 * 4, ksrc + j4);
            cp128(vdst + j4 * 4, vsrc + j4);
        }
    };

    stageKV(0, 0); CP_COMMIT();

    // stage Q once, fragment-major, scaled by exact 2^-3 (pre-rounded input)
    {
        const int d  = t >> 2;          // 0..63
        const int ic = (t & 3) * 32;
        const int kk = d >> 3, kc = d & 7;
        const int rbase = (kc >= 4) ? 2 : 0;
#pragma unroll
        for (int m = 0; m < 8; m++) {
            float4 v = *(const float4*)(qb + (size_t)d * LSEQ + i0 + ic + m * 4);
            float vv[4] = {v.x, v.y, v.z, v.w};
#pragma unroll
            for (int e = 0; e < 4; e++) {
                const int il = ic + m * 4 + e;
                const int wq = il >> 4, rr = il & 7, hi = (il >> 3) & 1;
                Qf[((kk * 8 + wq) * 32 + rr * 4 + (kc & 3)) * 4 + rbase + hi] = vv[e] * 0.125f;
            }
        }
    }

    float m0 = -1e30f, m1 = -1e30f, l0 = 0.0f, l1 = 0.0f;
    float o[8][4];
#pragma unroll
    for (int df = 0; df < 8; df++)
#pragma unroll
        for (int r = 0; r < 4; r++) o[df][r] = 0.0f;

    const int njt = LSEQ / 64;
    for (int jt = 0; jt < njt; jt++) {
        const int s = jt & 1;
        if (jt + 1 < njt) { stageKV(jt + 1, s ^ 1); CP_COMMIT(); CP_WAIT(1); }
        else { CP_WAIT(0); }
        __syncthreads();

        const float* Kb = KsA + s * KS_WORDS;
        const float* Vb = VsA + s * VS_WORDS;

        // ---- S = Q^T K ----
        float sreg[8][4];
#pragma unroll
        for (int nf = 0; nf < 8; nf++)
#pragma unroll
            for (int r = 0; r < 4; r++) sreg[nf][r] = 0.0f;

#pragma unroll
        for (int kk = 0; kk < 8; kk++) {
            float4 a = *(const float4*)&Qf[((kk * 8 + w) * 32 + lane) * 4];
            uint32_t a0 = fau(a.x), a1 = fau(a.y), a2 = fau(a.z), a3 = fau(a.w);
#pragma unroll
            for (int nf = 0; nf < 8; nf++) {
                uint32_t b0 = fau(Kb[(kk * 8 + qc)     * KP + nf * 8 + qr]);
                uint32_t b1 = fau(Kb[(kk * 8 + qc + 4) * KP + nf * 8 + qr]);
                mma_tf32(sreg[nf], a0, a1, a2, a3, b0, b1);
            }
        }

        // ---- online softmax (rows qr and qr+8 within warp's m16) ----
        float rm0 = -1e30f, rm1 = -1e30f;
#pragma unroll
        for (int nf = 0; nf < 8; nf++) {
            rm0 = fmaxf(rm0, fmaxf(sreg[nf][0], sreg[nf][1]));
            rm1 = fmaxf(rm1, fmaxf(sreg[nf][2], sreg[nf][3]));
        }
        rm0 = fmaxf(rm0, __shfl_xor_sync(0xffffffffu, rm0, 1));
        rm0 = fmaxf(rm0, __shfl_xor_sync(0xffffffffu, rm0, 2));
        rm1 = fmaxf(rm1, __shfl_xor_sync(0xffffffffu, rm1, 1));
        rm1 = fmaxf(rm1, __shfl_xor_sync(0xffffffffu, rm1, 2));

        const float mn0 = fmaxf(m0, rm0), mn1 = fmaxf(m1, rm1);
        const float al0 = __expf(m0 - mn0), al1 = __expf(m1 - mn1);
        m0 = mn0; m1 = mn1;

        float rs0 = 0.0f, rs1 = 0.0f;
#pragma unroll
        for (int nf = 0; nf < 8; nf++) {
            sreg[nf][0] = __expf(sreg[nf][0] - mn0);
            sreg[nf][1] = __expf(sreg[nf][1] - mn0);
            sreg[nf][2] = __expf(sreg[nf][2] - mn1);
            sreg[nf][3] = __expf(sreg[nf][3] - mn1);
            rs0 += sreg[nf][0] + sreg[nf][1];
            rs1 += sreg[nf][2] + sreg[nf][3];
        }
        rs0 += __shfl_xor_sync(0xffffffffu, rs0, 1);
        rs0 += __shfl_xor_sync(0xffffffffu, rs0, 2);
        rs1 += __shfl_xor_sync(0xffffffffu, rs1, 1);
        rs1 += __shfl_xor_sync(0xffffffffu, rs1, 2);

        l0 = l0 * al0 + rs0;
        l1 = l1 * al1 + rs1;
#pragma unroll
        for (int df = 0; df < 8; df++) {
            o[df][0] *= al0; o[df][1] *= al0;
            o[df][2] *= al1; o[df][3] *= al1;
        }

        // round P to tf32 in registers
#pragma unroll
        for (int nf = 0; nf < 8; nf++)
#pragma unroll
            for (int r = 0; r < 4; r++) sreg[nf][r] = tf32r(sreg[nf][r]);

        // ---- O += P @ V^T : P A-fragments via shfl permutation ----
        const int lsrc0 = (lane & ~3) | (qc >> 1);
        const int lsrc2 = lsrc0 + 2;
        const bool odd  = qc & 1;
#pragma unroll
        for (int kb2 = 0; kb2 < 8; kb2++) {
            float v00 = __shfl_sync(0xffffffffu, sreg[kb2][0], lsrc0);
            float v01 = __shfl_sync(0xffffffffu, sreg[kb2][1], lsrc0);
            float v10 = __shfl_sync(0xffffffffu, sreg[kb2][2], lsrc0);
            float v11 = __shfl_sync(0xffffffffu, sreg[kb2][3], lsrc0);
            float w00 = __shfl_sync(0xffffffffu, sreg[kb2][0], lsrc2);
            float w01 = __shfl_sync(0xffffffffu, sreg[kb2][1], lsrc2);
            float w10 = __shfl_sync(0xffffffffu, sreg[kb2][2], lsrc2);
            float w11 = __shfl_sync(0xffffffffu, sreg[kb2][3], lsrc2);
            uint32_t a0 = fau(odd ? v01 : v00);
            uint32_t a1 = fau(odd ? v11 : v10);
            uint32_t a2 = fau(odd ? w01 : w00);
            uint32_t a3 = fau(odd ? w11 : w10);
#pragma unroll
            for (int df = 0; df < 8; df++) {
                uint32_t b0 = fau(Vb[(df * 8 + qr) * VP + kb2 * 8 + qc]);
                uint32_t b1 = fau(Vb[(df * 8 + qr) * VP + kb2 * 8 + qc + 4]);
                mma_tf32(o[df], a0, a1, a2, a3, b0, b1);
            }
        }
        __syncthreads();   // reads of buf s done before next iter's cp.async refill
    }

    // epilogue: out[n, h*64 + d, i] = tf32r(O / l)
    const float inv0 = 1.0f / l0, inv1 = 1.0f / l1;
    const int gi = i0 + w * 16 + qr;
#pragma unroll
    for (int df = 0; df < 8; df++) {
        const int col = n * CH + h * DHEAD + df * 8 + qc * 2;
        out[(size_t)col * LSEQ + gi]           = tf32r(o[df][0] * inv0);
        out[(size_t)(col + 1) * LSEQ + gi]     = tf32r(o[df][1] * inv0);
        out[(size_t)col * LSEQ + gi + 8]       = tf32r(o[df][2] * inv1);
        out[(size_t)(col + 1) * LSEQ + gi + 8] = tf32r(o[df][3] * inv1);
    }
}

// ---------------------------------------------------------------------------
// Launch
// ---------------------------------------------------------------------------
extern "C" void kernel_launch(void* const* d_in, const int* in_sizes, int n_in,
                              void* d_out, int out_size)
{
    const float* x     = (const float*)d_in[0];   // [4, 512, 2048]
    const float* w_qkv = (const float*)d_in[1];   // [1536, 512]
    const float* w_out = (const float*)d_in[2];   // [512, 512]
    const float* b_out = (const float*)d_in[3];   // [512]
    float* out = (float*)d_out;                   // [4, 512, 2048]

    float *qkv, *att, *xr, *wqT, *woT;
    cudaGetSymbolAddress((void**)&qkv, g_qkv);
    cudaGetSymbolAddress((void**)&att, g_att);
    cudaGetSymbolAddress((void**)&xr,  g_x);
    cudaGetSymbolAddress((void**)&wqT, g_wqkvT);
    cudaGetSymbolAddress((void**)&woT, g_woutT);

    cudaFuncSetAttribute(gemm_cp, cudaFuncAttributeMaxDynamicSharedMemorySize, G_SMEM);
    cudaFuncSetAttribute(flash3,  cudaFuncAttributeMaxDynamicSharedMemorySize, FL_SMEM);

    // prep: round x; transpose+round weights
    {
        const int n4 = NB * CH * LSEQ / 4;
        round4_kernel<<<(n4 + 255) / 256, 256>>>((const float4*)x, (float4*)xr, n4);
        transpose_round<<<dim3(CH / 32, QKV_CH / 32), dim3(32, 8)>>>(w_qkv, wqT, QKV_CH, CH);
        transpose_round<<<dim3(CH / 32, CH / 32),     dim3(32, 8)>>>(w_out, woT, CH, CH);
    }

    // 1) qkv[n] = w_qkv @ x[n]   (tf32-rounded output)
    {
        dim3 grid(LSEQ / 128, QKV_CH / 128, NB);
        gemm_cp<<<grid, 256, G_SMEM>>>(wqT, xr, qkv, nullptr,
                                       QKV_CH, LSEQ, CH,
                                       (long)CH * LSEQ, (long)QKV_CH * LSEQ, 1);
    }
    // 2) flash attention -> att[n, (h d), l] (tf32-rounded output)
    {
        dim3 grid(LSEQ / 128, NB * NHEADS);
        flash3<<<grid, 256, FL_SMEM>>>(qkv, att);
    }
    // 3) out[n] = w_out @ att[n] + b_out
    {
        dim3 grid(LSEQ / 128, CH / 128, NB);
        gemm_cp<<<grid, 256, G_SMEM>>>(woT, att, out, b_out,
                                       CH, LSEQ, CH,
                                       (long)CH * LSEQ, (long)CH * LSEQ, 0);
    }
}

// round 4
// speedup vs baseline: 3.8014x; 1.1118x over previous
#include <cuda_runtime.h>
#include <math.h>
#include <stdint.h>

#define NB     4
#define CH     512
#define LSEQ   2048
#define NHEADS 8
#define DHEAD  64
#define QKV_CH 1536

// ---------------------------------------------------------------------------
// Scratch (no cudaMalloc allowed)
// ---------------------------------------------------------------------------
__device__ float g_qkv[(size_t)NB * QKV_CH * LSEQ];   // ~50 MB  (tf32-rounded)
__device__ float g_att[(size_t)NB * CH * LSEQ];       // ~17 MB  (tf32-rounded)
__device__ float g_x[(size_t)NB * CH * LSEQ];         // ~17 MB  (tf32-rounded x)
__device__ float g_wqkvT[CH * QKV_CH];                // w_qkv^T, rounded
__device__ float g_woutT[CH * CH];                    // w_out^T, rounded

// ---------------------------------------------------------------------------
// helpers
// ---------------------------------------------------------------------------
__device__ __forceinline__ float tf32r(float x) {
    uint32_t u;
    asm("cvt.rna.tf32.f32 %0, %1;" : "=r"(u) : "f"(x));
    return __uint_as_float(u);
}
__device__ __forceinline__ uint32_t fau(float x) { return __float_as_uint(x); }

__device__ __forceinline__ void mma_tf32(float c[4],
    uint32_t a0, uint32_t a1, uint32_t a2, uint32_t a3,
    uint32_t b0, uint32_t b1)
{
    asm volatile(
        "mma.sync.aligned.m16n8k8.row.col.f32.tf32.tf32.f32 "
        "{%0,%1,%2,%3}, {%4,%5,%6,%7}, {%8,%9}, {%0,%1,%2,%3};"
        : "+f"(c[0]), "+f"(c[1]), "+f"(c[2]), "+f"(c[3])
        : "r"(a0), "r"(a1), "r"(a2), "r"(a3), "r"(b0), "r"(b1));
}

__device__ __forceinline__ void cp128(uint32_t dst, const void* src) {
    asm volatile("cp.async.cg.shared.global [%0], [%1], 16;" :: "r"(dst), "l"(src));
}
#define CP_COMMIT() asm volatile("cp.async.commit_group;")
#define CP_WAIT(N)  asm volatile("cp.async.wait_group %0;" :: "n"(N))

// ---------------------------------------------------------------------------
// prep kernels
// ---------------------------------------------------------------------------
__global__ void round4_kernel(const float4* __restrict__ in, float4* __restrict__ out, int n4)
{
    int i = blockIdx.x * blockDim.x + threadIdx.x;
    if (i < n4) {
        float4 v = in[i];
        out[i] = make_float4(tf32r(v.x), tf32r(v.y), tf32r(v.z), tf32r(v.w));
    }
}

__global__ void transpose_round(const float* __restrict__ in, float* __restrict__ out,
                                int M, int K)
{
    __shared__ float tile[32][33];
    const int k0 = blockIdx.x * 32;
    const int m0 = blockIdx.y * 32;
    const int tx = threadIdx.x, ty = threadIdx.y;
#pragma unroll
    for (int r = 0; r < 32; r += 8)
        tile[ty + r][tx] = tf32r(in[(size_t)(m0 + ty + r) * K + k0 + tx]);
    __syncthreads();
#pragma unroll
    for (int r = 0; r < 32; r += 8)
        out[(size_t)(k0 + ty + r) * M + m0 + tx] = tile[tx][ty + r];
}

// ---------------------------------------------------------------------------
// GEMM (unchanged from round 3): 128x128 tile, 3-stage cp.async, tf32 mma
// ---------------------------------------------------------------------------
#define GP     136
#define GSTG   (16 * GP)
#define G_SMEM (2 * 3 * GSTG * (int)sizeof(float))

__global__ __launch_bounds__(256, 2)
void gemm_cp(const float* __restrict__ AT, const float* __restrict__ B,
             float* __restrict__ C, const float* __restrict__ bias,
             int M, int N, int K, long strideB, long strideC, int round_out)
{
    extern __shared__ float gsm[];
    float* Asm = gsm;
    float* Bsm = gsm + 3 * GSTG;

    const int t    = threadIdx.x;
    const int lane = t & 31;
    const int w    = t >> 5;
    const int qr   = lane >> 2;
    const int qc   = lane & 3;
    const int bm   = blockIdx.y * 128;
    const int bn   = blockIdx.x * 128;

    B += (long)blockIdx.z * strideB;
    C += (long)blockIdx.z * strideC;

    const int wm = (w >> 2) * 64;
    const int wn = (w & 3) * 32;

    const uint32_t aBase = (uint32_t)__cvta_generic_to_shared(Asm);
    const uint32_t bBase = (uint32_t)__cvta_generic_to_shared(Bsm);

    const int srow = t >> 4;
    const int scol = (t & 15) * 4;
    const int nslabs = K / 16;

    auto stage = [&](int slab, int buf) {
        const float* aSrc = AT + (size_t)(slab * 16 + srow) * M + bm + scol;
        const float* bSrc = B  + (size_t)(slab * 16 + srow) * N + bn + scol;
        uint32_t aDst = aBase + (uint32_t)((buf * GSTG + srow * GP + scol) * 4);
        uint32_t bDst = bBase + (uint32_t)((buf * GSTG + srow * GP + scol) * 4);
        cp128(aDst,       aSrc);
        cp128(aDst + 256, aSrc + 64);
        cp128(bDst,       bSrc);
        cp128(bDst + 256, bSrc + 64);
    };

    float acc[4][4][4];
#pragma unroll
    for (int i = 0; i < 4; i++)
#pragma unroll
        for (int j = 0; j < 4; j++)
#pragma unroll
            for (int r = 0; r < 4; r++) acc[i][j][r] = 0.0f;

    stage(0, 0); CP_COMMIT();
    stage(1, 1); CP_COMMIT();

    for (int i = 0; i < nslabs; i++) {
        const int s = i % 3;
        if (i + 2 < nslabs) { stage(i + 2, (i + 2) % 3); CP_COMMIT(); CP_WAIT(2); }
        else if (i + 1 < nslabs) { CP_WAIT(1); }
        else { CP_WAIT(0); }
        __syncthreads();

        const float* As = Asm + s * GSTG;
        const float* Bs = Bsm + s * GSTG;

#pragma unroll
        for (int ks = 0; ks < 16; ks += 8) {
            uint32_t af[4][4];
#pragma unroll
            for (int mf = 0; mf < 4; mf++) {
                const int mi = wm + mf * 16 + qr;
                af[mf][0] = fau(As[(ks + qc)     * GP + mi]);
                af[mf][1] = fau(As[(ks + qc)     * GP + mi + 8]);
                af[mf][2] = fau(As[(ks + qc + 4) * GP + mi]);
                af[mf][3] = fau(As[(ks + qc + 4) * GP + mi + 8]);
            }
#pragma unroll
            for (int nf = 0; nf < 4; nf++) {
                const int ni = wn + nf * 8 + qr;
                uint32_t b0 = fau(Bs[(ks + qc)     * GP + ni]);
                uint32_t b1 = fau(Bs[(ks + qc + 4) * GP + ni]);
#pragma unroll
                for (int mf = 0; mf < 4; mf++)
                    mma_tf32(acc[mf][nf], af[mf][0], af[mf][1], af[mf][2], af[mf][3], b0, b1);
            }
        }
        __syncthreads();
    }

#pragma unroll
    for (int mf = 0; mf < 4; mf++) {
        const int row = bm + wm + mf * 16 + qr;
        const float bv0 = bias ? bias[row]     : 0.0f;
        const float bv1 = bias ? bias[row + 8] : 0.0f;
#pragma unroll
        for (int nf = 0; nf < 4; nf++) {
            const int col = bn + wn + nf * 8 + qc * 2;
            float o00 = acc[mf][nf][0] + bv0, o01 = acc[mf][nf][1] + bv0;
            float o10 = acc[mf][nf][2] + bv1, o11 = acc[mf][nf][3] + bv1;
            if (round_out) {
                o00 = tf32r(o00); o01 = tf32r(o01);
                o10 = tf32r(o10); o11 = tf32r(o11);
            }
            *(float2*)(C + (size_t)row * N + col)       = make_float2(o00, o01);
            *(float2*)(C + (size_t)(row + 8) * N + col) = make_float2(o10, o11);
        }
    }
}

// ---------------------------------------------------------------------------
// Flash attention v4: Bq=256, 256 threads, 8 warps x m32n64 (2 m-frags/warp).
// K/V B-fragments feed TWO mma's each -> crossbar traffic per output row
// halved vs v3. Q staged once fragment-major. K/V double-buffered cp.async.
// P stays in registers (shfl permutation). All inputs pre-rounded tf32.
// ---------------------------------------------------------------------------
#define KP        72
#define VP        68
#define QF_WORDS  (8 * 16 * 32 * 4)         // 16384 (256 rows)
#define KS_WORDS  (64 * KP)                 // 4608
#define VS_WORDS  (64 * VP)                 // 4352
#define FL_SMEM   ((QF_WORDS + 2 * KS_WORDS + 2 * VS_WORDS) * (int)sizeof(float)) // 137216

__global__ __launch_bounds__(256, 1)
void flash4(const float* __restrict__ qkv, float* __restrict__ out)
{
    extern __shared__ float sm[];
    float* Qf  = sm;                          // [kk=8][m16blk=16][lane=32][4]
    float* KsA = sm + QF_WORDS;               // [2][64][72]
    float* VsA = KsA + 2 * KS_WORDS;          // [2][64][68]

    const int t    = threadIdx.x;
    const int lane = t & 31;
    const int w    = t >> 5;      // 0..7
    const int qr   = lane >> 2;   // 0..7
    const int qc   = lane & 3;    // 0..3
    const int i0   = blockIdx.x * 256;
    const int nh   = blockIdx.y;
    const int n    = nh >> 3, h = nh & 7;

    const float* qb = qkv + ((size_t)n * QKV_CH + h * DHEAD) * LSEQ;
    const float* kb = qb + (size_t)CH * LSEQ;
    const float* vb = qb + 2 * (size_t)CH * LSEQ;

    const uint32_t ksBase = (uint32_t)__cvta_generic_to_shared(KsA);
    const uint32_t vsBase = (uint32_t)__cvta_generic_to_shared(VsA);

    const int sd = t >> 2;        // staging row d: 0..63
    const int sc = t & 3;

    auto stageKV = [&](int jt, int buf) {
        const float* ksrc = kb + (size_t)sd * LSEQ + jt * 64;
        const float* vsrc = vb + (size_t)sd * LSEQ + jt * 64;
        uint32_t kdst = ksBase + (uint32_t)((buf * KS_WORDS + sd * KP) * 4);
        uint32_t vdst = vsBase + (uint32_t)((buf * VS_WORDS + sd * VP) * 4);
#pragma unroll
        for (int c = 0; c < 4; c++) {
            const int j4 = (sc + 4 * c) * 4;
            cp128(kdst + j4 * 4, ksrc + j4);
            cp128(vdst + j4 * 4, vsrc + j4);
        }
    };

    stageKV(0, 0); CP_COMMIT();

    // stage Q once, fragment-major (256 rows), scaled by exact 2^-3
    {
        const int d  = t >> 2;          // 0..63
        const int ic = (t & 3) * 64;    // 64 i-values per thread
        const int kk = d >> 3, kc = d & 7;
        const int rbase = (kc >= 4) ? 2 : 0;
#pragma unroll
        for (int m = 0; m < 16; m++) {
            float4 v = *(const float4*)(qb + (size_t)d * LSEQ + i0 + ic + m * 4);
            float vv[4] = {v.x, v.y, v.z, v.w};
#pragma unroll
            for (int e = 0; e < 4; e++) {
                const int il = ic + m * 4 + e;             // 0..255
                const int wq = il >> 4, rr = il & 7, hi = (il >> 3) & 1;
                Qf[((kk * 16 + wq) * 32 + rr * 4 + (kc & 3)) * 4 + rbase + hi] = vv[e] * 0.125f;
            }
        }
    }

    float mrow[2][2], lrow[2][2];
    float o[2][8][4];
#pragma unroll
    for (int mf = 0; mf < 2; mf++) {
        mrow[mf][0] = -1e30f; mrow[mf][1] = -1e30f;
        lrow[mf][0] = 0.0f;   lrow[mf][1] = 0.0f;
#pragma unroll
        for (int df = 0; df < 8; df++)
#pragma unroll
            for (int r = 0; r < 4; r++) o[mf][df][r] = 0.0f;
    }

    const int njt = LSEQ / 64;
    for (int jt = 0; jt < njt; jt++) {
        const int s = jt & 1;
        if (jt + 1 < njt) { stageKV(jt + 1, s ^ 1); CP_COMMIT(); CP_WAIT(1); }
        else { CP_WAIT(0); }
        __syncthreads();

        const float* Kb = KsA + s * KS_WORDS;
        const float* Vb = VsA + s * VS_WORDS;

        // ---- S = Q^T K  (warp rows [w*32, w*32+32)) ----
        float sreg[2][8][4];
#pragma unroll
        for (int mf = 0; mf < 2; mf++)
#pragma unroll
            for (int nf = 0; nf < 8; nf++)
#pragma unroll
                for (int r = 0; r < 4; r++) sreg[mf][nf][r] = 0.0f;

#pragma unroll
        for (int kk = 0; kk < 8; kk++) {
            float4 aA = *(const float4*)&Qf[((kk * 16 + w * 2 + 0) * 32 + lane) * 4];
            float4 aB = *(const float4*)&Qf[((kk * 16 + w * 2 + 1) * 32 + lane) * 4];
            uint32_t a00 = fau(aA.x), a01 = fau(aA.y), a02 = fau(aA.z), a03 = fau(aA.w);
            uint32_t a10 = fau(aB.x), a11 = fau(aB.y), a12 = fau(aB.z), a13 = fau(aB.w);
#pragma unroll
            for (int nf = 0; nf < 8; nf++) {
                uint32_t b0 = fau(Kb[(kk * 8 + qc)     * KP + nf * 8 + qr]);
                uint32_t b1 = fau(Kb[(kk * 8 + qc + 4) * KP + nf * 8 + qr]);
                mma_tf32(sreg[0][nf], a00, a01, a02, a03, b0, b1);
                mma_tf32(sreg[1][nf], a10, a11, a12, a13, b0, b1);
            }
        }

        // ---- online softmax, per m-frag ----
#pragma unroll
        for (int mf = 0; mf < 2; mf++) {
            float rm0 = -1e30f, rm1 = -1e30f;
#pragma unroll
            for (int nf = 0; nf < 8; nf++) {
                rm0 = fmaxf(rm0, fmaxf(sreg[mf][nf][0], sreg[mf][nf][1]));
                rm1 = fmaxf(rm1, fmaxf(sreg[mf][nf][2], sreg[mf][nf][3]));
            }
            rm0 = fmaxf(rm0, __shfl_xor_sync(0xffffffffu, rm0, 1));
            rm0 = fmaxf(rm0, __shfl_xor_sync(0xffffffffu, rm0, 2));
            rm1 = fmaxf(rm1, __shfl_xor_sync(0xffffffffu, rm1, 1));
            rm1 = fmaxf(rm1, __shfl_xor_sync(0xffffffffu, rm1, 2));

            const float mn0 = fmaxf(mrow[mf][0], rm0);
            const float mn1 = fmaxf(mrow[mf][1], rm1);
            const float al0 = __expf(mrow[mf][0] - mn0);
            const float al1 = __expf(mrow[mf][1] - mn1);
            mrow[mf][0] = mn0; mrow[mf][1] = mn1;

            float rs0 = 0.0f, rs1 = 0.0f;
#pragma unroll
            for (int nf = 0; nf < 8; nf++) {
                sreg[mf][nf][0] = __expf(sreg[mf][nf][0] - mn0);
                sreg[mf][nf][1] = __expf(sreg[mf][nf][1] - mn0);
                sreg[mf][nf][2] = __expf(sreg[mf][nf][2] - mn1);
                sreg[mf][nf][3] = __expf(sreg[mf][nf][3] - mn1);
                rs0 += sreg[mf][nf][0] + sreg[mf][nf][1];
                rs1 += sreg[mf][nf][2] + sreg[mf][nf][3];
            }
            rs0 += __shfl_xor_sync(0xffffffffu, rs0, 1);
            rs0 += __shfl_xor_sync(0xffffffffu, rs0, 2);
            rs1 += __shfl_xor_sync(0xffffffffu, rs1, 1);
            rs1 += __shfl_xor_sync(0xffffffffu, rs1, 2);

            lrow[mf][0] = lrow[mf][0] * al0 + rs0;
            lrow[mf][1] = lrow[mf][1] * al1 + rs1;
#pragma unroll
            for (int df = 0; df < 8; df++) {
                o[mf][df][0] *= al0; o[mf][df][1] *= al0;
                o[mf][df][2] *= al1; o[mf][df][3] *= al1;
            }
            // round P to tf32 in registers
#pragma unroll
            for (int nf = 0; nf < 8; nf++)
#pragma unroll
                for (int r = 0; r < 4; r++) sreg[mf][nf][r] = tf32r(sreg[mf][nf][r]);
        }

        // ---- O += P @ V^T ----
        const int lsrc0 = (lane & ~3) | (qc >> 1);
        const int lsrc2 = lsrc0 + 2;
        const bool odd  = qc & 1;
#pragma unroll
        for (int kb2 = 0; kb2 < 8; kb2++) {
            uint32_t af[2][4];
#pragma unroll
            for (int mf = 0; mf < 2; mf++) {
                float v00 = __shfl_sync(0xffffffffu, sreg[mf][kb2][0], lsrc0);
                float v01 = __shfl_sync(0xffffffffu, sreg[mf][kb2][1], lsrc0);
                float v10 = __shfl_sync(0xffffffffu, sreg[mf][kb2][2], lsrc0);
                float v11 = __shfl_sync(0xffffffffu, sreg[mf][kb2][3], lsrc0);
                float w00 = __shfl_sync(0xffffffffu, sreg[mf][kb2][0], lsrc2);
                float w01 = __shfl_sync(0xffffffffu, sreg[mf][kb2][1], lsrc2);
                float w10 = __shfl_sync(0xffffffffu, sreg[mf][kb2][2], lsrc2);
                float w11 = __shfl_sync(0xffffffffu, sreg[mf][kb2][3], lsrc2);
                af[mf][0] = fau(odd ? v01 : v00);
                af[mf][1] = fau(odd ? v11 : v10);
                af[mf][2] = fau(odd ? w01 : w00);
                af[mf][3] = fau(odd ? w11 : w10);
            }
#pragma unroll
            for (int df = 0; df < 8; df++) {
                uint32_t b0 = fau(Vb[(df * 8 + qr) * VP + kb2 * 8 + qc]);
                uint32_t b1 = fau(Vb[(df * 8 + qr) * VP + kb2 * 8 + qc + 4]);
                mma_tf32(o[0][df], af[0][0], af[0][1], af[0][2], af[0][3], b0, b1);
                mma_tf32(o[1][df], af[1][0], af[1][1], af[1][2], af[1][3], b0, b1);
            }
        }
        __syncthreads();
    }

    // epilogue
#pragma unroll
    for (int mf = 0; mf < 2; mf++) {
        const float inv0 = 1.0f / lrow[mf][0], inv1 = 1.0f / lrow[mf][1];
        const int gi = i0 + w * 32 + mf * 16 + qr;
#pragma unroll
        for (int df = 0; df < 8; df++) {
            const int col = n * CH + h * DHEAD + df * 8 + qc * 2;
            out[(size_t)col * LSEQ + gi]           = tf32r(o[mf][df][0] * inv0);
            out[(size_t)(col + 1) * LSEQ + gi]     = tf32r(o[mf][df][1] * inv0);
            out[(size_t)col * LSEQ + gi + 8]       = tf32r(o[mf][df][2] * inv1);
            out[(size_t)(col + 1) * LSEQ + gi + 8] = tf32r(o[mf][df][3] * inv1);
        }
    }
}

// ---------------------------------------------------------------------------
// Launch
// ---------------------------------------------------------------------------
extern "C" void kernel_launch(void* const* d_in, const int* in_sizes, int n_in,
                              void* d_out, int out_size)
{
    const float* x     = (const float*)d_in[0];
    const float* w_qkv = (const float*)d_in[1];
    const float* w_out = (const float*)d_in[2];
    const float* b_out = (const float*)d_in[3];
    float* out = (float*)d_out;

    float *qkv, *att, *xr, *wqT, *woT;
    cudaGetSymbolAddress((void**)&qkv, g_qkv);
    cudaGetSymbolAddress((void**)&att, g_att);
    cudaGetSymbolAddress((void**)&xr,  g_x);
    cudaGetSymbolAddress((void**)&wqT, g_wqkvT);
    cudaGetSymbolAddress((void**)&woT, g_woutT);

    cudaFuncSetAttribute(gemm_cp, cudaFuncAttributeMaxDynamicSharedMemorySize, G_SMEM);
    cudaFuncSetAttribute(flash4,  cudaFuncAttributeMaxDynamicSharedMemorySize, FL_SMEM);

    // prep
    {
        const int n4 = NB * CH * LSEQ / 4;
        round4_kernel<<<(n4 + 255) / 256, 256>>>((const float4*)x, (float4*)xr, n4);
        transpose_round<<<dim3(CH / 32, QKV_CH / 32), dim3(32, 8)>>>(w_qkv, wqT, QKV_CH, CH);
        transpose_round<<<dim3(CH / 32, CH / 32),     dim3(32, 8)>>>(w_out, woT, CH, CH);
    }

    // 1) qkv[n] = w_qkv @ x[n]   (tf32-rounded output)
    {
        dim3 grid(LSEQ / 128, QKV_CH / 128, NB);
        gemm_cp<<<grid, 256, G_SMEM>>>(wqT, xr, qkv, nullptr,
                                       QKV_CH, LSEQ, CH,
                                       (long)CH * LSEQ, (long)QKV_CH * LSEQ, 1);
    }
    // 2) flash attention -> att[n, (h d), l]
    {
        dim3 grid(LSEQ / 256, NB * NHEADS);
        flash4<<<grid, 256, FL_SMEM>>>(qkv, att);
    }
    // 3) out[n] = w_out @ att[n] + b_out
    {
        dim3 grid(LSEQ / 128, CH / 128, NB);
        gemm_cp<<<grid, 256, G_SMEM>>>(woT, att, out, b_out,
                                       CH, LSEQ, CH,
                                       (long)CH * LSEQ, (long)CH * LSEQ, 0);
    }
}